// round 1
// baseline (speedup 1.0000x reference)
#include <cuda_runtime.h>
#include <math.h>
#include <stdint.h>

// Problem constants
#define Bq 2048
#define Iq 1024
#define Hq 2048
#define Cq 1000
#define Sq 8
#define N1 (Sq * 2 * Hq)   // 32768
#define TOPKq 256
#define EPSq 1e-8f

// ---------------- scratch (device globals; no allocation allowed) ----------
__device__ float g_act[(size_t)Bq * N1];   // [B, S*2H] post-exp activations (256 MB)
__device__ float g_norm[Bq * Sq];          // per (b,s) sum of g^2
__device__ float g_cphi[Sq * Hq];
__device__ float g_sphi[Sq * Hq];
__device__ float g_supr[Bq * Hq];
__device__ float g_supi[Bq * Hq];
__device__ float g_mag[Bq * Hq];           // mag, later reused for mag_sq
__device__ float g_probs[Bq * Hq];

// ---------------- small helpers --------------------------------------------
__global__ void zero_norm_kernel() {
    int i = blockIdx.x * blockDim.x + threadIdx.x;
    if (i < Bq * Sq) g_norm[i] = 0.0f;
}

__global__ void sincos_kernel(const float* __restrict__ phases) {
    int i = blockIdx.x * blockDim.x + threadIdx.x;
    if (i < Sq * Hq) {
        float s, c;
        sincosf(phases[i], &s, &c);
        g_cphi[i] = c;
        g_sphi[i] = s;
    }
}

// ---------------- GEMM1: act = exp(-(x @ W^T + b)^2), norm accumulation ----
// M=2048 (B), N=32768 (S*2H), K=1024. 128x128x16 tile, 8x8 per thread.
__global__ __launch_bounds__(256) void gemm1_kernel(
    const float* __restrict__ X, const float* __restrict__ W,
    const float* __restrict__ bias)
{
    const int BK = 16;
    __shared__ float As[BK][128];
    __shared__ float Bs[BK][128];

    int tid = threadIdx.x;
    int tx = tid & 15, ty = tid >> 4;
    int mBase = blockIdx.y * 128;
    int nBase = blockIdx.x * 128;

    float acc[8][8];
#pragma unroll
    for (int i = 0; i < 8; i++)
#pragma unroll
        for (int j = 0; j < 8; j++) acc[i][j] = 0.0f;

    const float* Aptr = X + (size_t)mBase * Iq;
    const float* Bptr = W + (size_t)nBase * Iq;

    for (int kt = 0; kt < Iq; kt += BK) {
#pragma unroll
        for (int l = 0; l < 2; l++) {
            int f = tid + l * 256;
            int row = f >> 2, c4 = f & 3;
            float4 v = *(const float4*)(Aptr + (size_t)row * Iq + kt + c4 * 4);
            As[c4 * 4 + 0][row] = v.x; As[c4 * 4 + 1][row] = v.y;
            As[c4 * 4 + 2][row] = v.z; As[c4 * 4 + 3][row] = v.w;
        }
#pragma unroll
        for (int l = 0; l < 2; l++) {
            int f = tid + l * 256;
            int row = f >> 2, c4 = f & 3;
            float4 v = *(const float4*)(Bptr + (size_t)row * Iq + kt + c4 * 4);
            Bs[c4 * 4 + 0][row] = v.x; Bs[c4 * 4 + 1][row] = v.y;
            Bs[c4 * 4 + 2][row] = v.z; Bs[c4 * 4 + 3][row] = v.w;
        }
        __syncthreads();
#pragma unroll
        for (int k = 0; k < BK; k++) {
            float a[8], bb[8];
            *(float4*)&a[0]  = *(const float4*)&As[k][ty * 8];
            *(float4*)&a[4]  = *(const float4*)&As[k][ty * 8 + 4];
            *(float4*)&bb[0] = *(const float4*)&Bs[k][tx * 8];
            *(float4*)&bb[4] = *(const float4*)&Bs[k][tx * 8 + 4];
#pragma unroll
            for (int i = 0; i < 8; i++)
#pragma unroll
                for (int j = 0; j < 8; j++) acc[i][j] += a[i] * bb[j];
        }
        __syncthreads();
    }

    // epilogue: bias, exp(-v^2), store, per-(row,s) norm accumulation
    int sIdx = nBase >> 12;  // nBase / 4096; BN=128 divides 4096 -> single s per block
#pragma unroll
    for (int i = 0; i < 8; i++) {
        int m = mBase + ty * 8 + i;
        int n0 = nBase + tx * 8;
        float rs = 0.0f;
        float gvals[8];
#pragma unroll
        for (int j = 0; j < 8; j++) {
            float v = acc[i][j] + bias[n0 + j];
            float g = expf(-v * v);
            gvals[j] = g;
            rs += g * g;
        }
        float4* dst = (float4*)&g_act[(size_t)m * N1 + n0];
        dst[0] = make_float4(gvals[0], gvals[1], gvals[2], gvals[3]);
        dst[1] = make_float4(gvals[4], gvals[5], gvals[6], gvals[7]);
        // reduce rs over the 16 tx threads (sub-warp groups of 16)
#pragma unroll
        for (int off = 8; off; off >>= 1)
            rs += __shfl_down_sync(0xffffffffu, rs, off, 16);
        if (tx == 0) atomicAdd(&g_norm[m * Sq + sIdx], rs);
    }
}

// ---------------- superposition: phase mix + normalize ---------------------
__global__ __launch_bounds__(256) void sup_kernel() {
    int idx = blockIdx.x * blockDim.x + threadIdx.x;  // < B*H
    int b = idx >> 11, h = idx & (Hq - 1);
    float r = 0.0f, im = 0.0f;
#pragma unroll
    for (int s = 0; s < Sq; s++) {
        float f  = rsqrtf(g_norm[b * Sq + s] + EPSq);
        float a  = g_act[(size_t)b * N1 + s * (2 * Hq) + h];
        float be = g_act[(size_t)b * N1 + s * (2 * Hq) + Hq + h];
        float c  = g_cphi[s * Hq + h];
        float sp = g_sphi[s * Hq + h];
        r  += f * (a * c - be * sp);
        im += f * (a * sp + be * c);
    }
    g_supr[idx] = r;
    g_supi[idx] = im;
}

__global__ __launch_bounds__(256) void mag_kernel() {
    int idx = blockIdx.x * blockDim.x + threadIdx.x;
    float r = g_supr[idx], im = g_supi[idx];
    g_mag[idx] = sqrtf(r * r + im * im);
}

__global__ __launch_bounds__(256) void msq_kernel() {
    int idx = blockIdx.x * blockDim.x + threadIdx.x;
    float r = g_supr[idx], im = g_supi[idx];
    g_mag[idx] = r * r + im * im;
}

// ---------------- gate GEMM: gate = sigmoid(mag @ gate_W^T + gate_b) -------
// epilogue updates supr/supi in place. M=N=K=2048.
__global__ __launch_bounds__(256) void gemm_gate_kernel(
    const float* __restrict__ GW, const float* __restrict__ gb)
{
    const int BK = 16;
    __shared__ float As[BK][128];
    __shared__ float Bs[BK][128];

    int tid = threadIdx.x;
    int tx = tid & 15, ty = tid >> 4;
    int mBase = blockIdx.y * 128;
    int nBase = blockIdx.x * 128;

    float acc[8][8];
#pragma unroll
    for (int i = 0; i < 8; i++)
#pragma unroll
        for (int j = 0; j < 8; j++) acc[i][j] = 0.0f;

    const float* Aptr = g_mag + (size_t)mBase * Hq;
    const float* Bptr = GW + (size_t)nBase * Hq;

    for (int kt = 0; kt < Hq; kt += BK) {
#pragma unroll
        for (int l = 0; l < 2; l++) {
            int f = tid + l * 256;
            int row = f >> 2, c4 = f & 3;
            float4 v = *(const float4*)(Aptr + (size_t)row * Hq + kt + c4 * 4);
            As[c4 * 4 + 0][row] = v.x; As[c4 * 4 + 1][row] = v.y;
            As[c4 * 4 + 2][row] = v.z; As[c4 * 4 + 3][row] = v.w;
        }
#pragma unroll
        for (int l = 0; l < 2; l++) {
            int f = tid + l * 256;
            int row = f >> 2, c4 = f & 3;
            float4 v = *(const float4*)(Bptr + (size_t)row * Hq + kt + c4 * 4);
            Bs[c4 * 4 + 0][row] = v.x; Bs[c4 * 4 + 1][row] = v.y;
            Bs[c4 * 4 + 2][row] = v.z; Bs[c4 * 4 + 3][row] = v.w;
        }
        __syncthreads();
#pragma unroll
        for (int k = 0; k < BK; k++) {
            float a[8], bb[8];
            *(float4*)&a[0]  = *(const float4*)&As[k][ty * 8];
            *(float4*)&a[4]  = *(const float4*)&As[k][ty * 8 + 4];
            *(float4*)&bb[0] = *(const float4*)&Bs[k][tx * 8];
            *(float4*)&bb[4] = *(const float4*)&Bs[k][tx * 8 + 4];
#pragma unroll
            for (int i = 0; i < 8; i++)
#pragma unroll
                for (int j = 0; j < 8; j++) acc[i][j] += a[i] * bb[j];
        }
        __syncthreads();
    }

#pragma unroll
    for (int i = 0; i < 8; i++) {
        int m = mBase + ty * 8 + i;
#pragma unroll
        for (int j = 0; j < 8; j++) {
            int n = nBase + tx * 8 + j;
            float v = acc[i][j] + gb[n];
            float g = 1.0f / (1.0f + expf(-v));
            size_t idx = (size_t)m * Hq + n;
            g_supr[idx] *= g;
            g_supi[idx] *= g;
        }
    }
}

// ---------------- exact top-k (k=256 of 2048) per row, jax tie semantics ---
__global__ __launch_bounds__(256) void topk_kernel() {
    __shared__ float sv[Hq];
    __shared__ int swarp[8];
    __shared__ float fwarp[8];
    __shared__ int scnt;
    __shared__ float ssum;

    int b = blockIdx.x;
    int t = threadIdx.x;
    for (int i = t; i < Hq; i += 256) sv[i] = g_mag[(size_t)b * Hq + i];
    __syncthreads();

    // find 256th-largest via bitwise threshold search (values are >= 0)
    unsigned thr = 0u;
    for (int bit = 30; bit >= 0; --bit) {
        unsigned cand = thr | (1u << bit);
        int c = 0;
        for (int i = t; i < Hq; i += 256)
            c += (__float_as_uint(sv[i]) >= cand) ? 1 : 0;
#pragma unroll
        for (int o = 16; o; o >>= 1) c += __shfl_down_sync(0xffffffffu, c, o);
        if ((t & 31) == 0) swarp[t >> 5] = c;
        __syncthreads();
        if (t < 32) {
            int cc = (t < 8) ? swarp[t] : 0;
#pragma unroll
            for (int o = 4; o; o >>= 1) cc += __shfl_down_sync(0xffffffffu, cc, o);
            if (t == 0) scnt = cc;
        }
        __syncthreads();
        if (scnt >= TOPKq) thr = cand;
        __syncthreads();
    }
    float T = __uint_as_float(thr);

    // count strictly greater than T
    {
        int c = 0;
        for (int i = t; i < Hq; i += 256) c += (sv[i] > T) ? 1 : 0;
#pragma unroll
        for (int o = 16; o; o >>= 1) c += __shfl_down_sync(0xffffffffu, c, o);
        if ((t & 31) == 0) swarp[t >> 5] = c;
        __syncthreads();
        if (t < 32) {
            int cc = (t < 8) ? swarp[t] : 0;
#pragma unroll
            for (int o = 4; o; o >>= 1) cc += __shfl_down_sync(0xffffffffu, cc, o);
            if (t == 0) scnt = cc;
        }
        __syncthreads();
    }
    int need_eq = TOPKq - scnt;  // how many values equal to T we keep (lowest index first)
    __syncthreads();

    // keep mask + masked sum
    float vals[8];
    bool keep[8];
    float mysum = 0.0f;
#pragma unroll
    for (int l = 0; l < 8; l++) {
        int i = t + l * 256;
        float v = sv[i];
        bool k;
        if (v > T) k = true;
        else if (v == T) {
            int r = 0;
            for (int j = 0; j < i; j++) r += (sv[j] == T) ? 1 : 0;
            k = (r < need_eq);
        } else k = false;
        vals[l] = v;
        keep[l] = k;
        if (k) mysum += v;
    }
#pragma unroll
    for (int o = 16; o; o >>= 1) mysum += __shfl_down_sync(0xffffffffu, mysum, o);
    if ((t & 31) == 0) fwarp[t >> 5] = mysum;
    __syncthreads();
    if (t < 32) {
        float ss = (t < 8) ? fwarp[t] : 0.0f;
#pragma unroll
        for (int o = 4; o; o >>= 1) ss += __shfl_down_sync(0xffffffffu, ss, o);
        if (t == 0) ssum = ss;
    }
    __syncthreads();
    float denom = ssum + EPSq;
#pragma unroll
    for (int l = 0; l < 8; l++) {
        int i = t + l * 256;
        g_probs[(size_t)b * Hq + i] = keep[l] ? vals[l] / denom : 0.0f;
    }
}

// ---------------- classifier GEMM: logits = probs @ clf_W^T + clf_b --------
// M=2048, N=1000 (bounds), K=2048
__global__ __launch_bounds__(256) void gemm_clf_kernel(
    const float* __restrict__ CW, const float* __restrict__ cb,
    float* __restrict__ out)
{
    const int BK = 16;
    __shared__ float As[BK][128];
    __shared__ float Bs[BK][128];

    int tid = threadIdx.x;
    int tx = tid & 15, ty = tid >> 4;
    int mBase = blockIdx.y * 128;
    int nBase = blockIdx.x * 128;

    float acc[8][8];
#pragma unroll
    for (int i = 0; i < 8; i++)
#pragma unroll
        for (int j = 0; j < 8; j++) acc[i][j] = 0.0f;

    const float* Aptr = g_probs + (size_t)mBase * Hq;

    for (int kt = 0; kt < Hq; kt += BK) {
#pragma unroll
        for (int l = 0; l < 2; l++) {
            int f = tid + l * 256;
            int row = f >> 2, c4 = f & 3;
            float4 v = *(const float4*)(Aptr + (size_t)row * Hq + kt + c4 * 4);
            As[c4 * 4 + 0][row] = v.x; As[c4 * 4 + 1][row] = v.y;
            As[c4 * 4 + 2][row] = v.z; As[c4 * 4 + 3][row] = v.w;
        }
#pragma unroll
        for (int l = 0; l < 2; l++) {
            int f = tid + l * 256;
            int row = f >> 2, c4 = f & 3;
            int nglob = nBase + row;
            float4 v = make_float4(0.f, 0.f, 0.f, 0.f);
            if (nglob < Cq)
                v = *(const float4*)(CW + (size_t)nglob * Hq + kt + c4 * 4);
            Bs[c4 * 4 + 0][row] = v.x; Bs[c4 * 4 + 1][row] = v.y;
            Bs[c4 * 4 + 2][row] = v.z; Bs[c4 * 4 + 3][row] = v.w;
        }
        __syncthreads();
#pragma unroll
        for (int k = 0; k < BK; k++) {
            float a[8], bb[8];
            *(float4*)&a[0]  = *(const float4*)&As[k][ty * 8];
            *(float4*)&a[4]  = *(const float4*)&As[k][ty * 8 + 4];
            *(float4*)&bb[0] = *(const float4*)&Bs[k][tx * 8];
            *(float4*)&bb[4] = *(const float4*)&Bs[k][tx * 8 + 4];
#pragma unroll
            for (int i = 0; i < 8; i++)
#pragma unroll
                for (int j = 0; j < 8; j++) acc[i][j] += a[i] * bb[j];
        }
        __syncthreads();
    }

#pragma unroll
    for (int i = 0; i < 8; i++) {
        int m = mBase + ty * 8 + i;
#pragma unroll
        for (int j = 0; j < 8; j++) {
            int n = nBase + tx * 8 + j;
            if (n < Cq) out[(size_t)m * Cq + n] = acc[i][j] + cb[n];
        }
    }
}

// ---------------- launch ----------------------------------------------------
extern "C" void kernel_launch(void* const* d_in, const int* in_sizes, int n_in,
                              void* d_out, int out_size)
{
    const float* x      = (const float*)d_in[0];
    const float* W      = (const float*)d_in[1];
    const float* bias   = (const float*)d_in[2];
    const float* phases = (const float*)d_in[3];
    const float* gate_W = (const float*)d_in[4];
    const float* gate_b = (const float*)d_in[5];
    const float* clf_W  = (const float*)d_in[6];
    const float* clf_b  = (const float*)d_in[7];
    float* out = (float*)d_out;

    zero_norm_kernel<<<(Bq * Sq + 255) / 256, 256>>>();
    sincos_kernel<<<(Sq * Hq + 255) / 256, 256>>>(phases);

    dim3 g1(N1 / 128, Bq / 128);  // (256, 16)
    gemm1_kernel<<<g1, 256>>>(x, W, bias);

    sup_kernel<<<(Bq * Hq) / 256, 256>>>();

    for (int step = 0; step < 2; step++) {
        mag_kernel<<<(Bq * Hq) / 256, 256>>>();
        dim3 gg(Hq / 128, Bq / 128);  // (16, 16)
        gemm_gate_kernel<<<gg, 256>>>(gate_W, gate_b);
    }

    msq_kernel<<<(Bq * Hq) / 256, 256>>>();
    topk_kernel<<<Bq, 256>>>();

    dim3 gc((Cq + 127) / 128, Bq / 128);  // (8, 16)
    gemm_clf_kernel<<<gc, 256>>>(clf_W, clf_b, out);
}

// round 3
// speedup vs baseline: 2.7458x; 2.7458x over previous
#include <cuda_runtime.h>
#include <cuda_bf16.h>
#include <math.h>
#include <stdint.h>

// Problem constants
#define Bq 2048
#define Iq 1024
#define Hq 2048
#define Cq 1000
#define Sq 8
#define N1 (Sq * 2 * Hq)   // 32768
#define TOPKq 256
#define EPSq 1e-8f

// ---------------- scratch (device globals; no allocation allowed) ----------
__device__ float g_act[(size_t)Bq * N1];   // [B, S*2H] post-exp activations
__device__ float g_norm[Bq * Sq];
__device__ float g_cphi[Sq * Hq];
__device__ float g_sphi[Sq * Hq];
__device__ float g_supr[Bq * Hq];
__device__ float g_supi[Bq * Hq];
__device__ float g_mag[Bq * Hq];           // mag_sq for topk

// bf16 hi/lo splits for tensor-core fp32 emulation
__device__ __align__(16) __nv_bfloat16 g_xhi[(size_t)Bq * Iq];
__device__ __align__(16) __nv_bfloat16 g_xlo[(size_t)Bq * Iq];
__device__ __align__(16) __nv_bfloat16 g_whi[(size_t)N1 * Iq];
__device__ __align__(16) __nv_bfloat16 g_wlo[(size_t)N1 * Iq];
__device__ __align__(16) __nv_bfloat16 g_gwhi[(size_t)Hq * Hq];
__device__ __align__(16) __nv_bfloat16 g_gwlo[(size_t)Hq * Hq];
__device__ __align__(16) __nv_bfloat16 g_cwhi[(size_t)Cq * Hq];
__device__ __align__(16) __nv_bfloat16 g_cwlo[(size_t)Cq * Hq];
__device__ __align__(16) __nv_bfloat16 g_mhi[(size_t)Bq * Hq];
__device__ __align__(16) __nv_bfloat16 g_mlo[(size_t)Bq * Hq];
__device__ __align__(16) __nv_bfloat16 g_pbhi[(size_t)Bq * Hq];
__device__ __align__(16) __nv_bfloat16 g_pblo[(size_t)Bq * Hq];

// ---------------- PTX helpers ----------------------------------------------
__device__ __forceinline__ uint32_t smem_u32(const void* p) {
    uint32_t a;
    asm("{ .reg .u64 t; cvta.to.shared.u64 t, %1; cvt.u32.u64 %0, t; }" : "=r"(a) : "l"(p));
    return a;
}

#define CP16(dst, src, szr) \
    asm volatile("cp.async.cg.shared.global [%0], [%1], 16, %2;" \
                 :: "r"(dst), "l"(src), "r"(szr) : "memory")
#define CP_COMMIT() asm volatile("cp.async.commit_group;" ::: "memory")
#define CP_WAIT1()  asm volatile("cp.async.wait_group 1;" ::: "memory")
#define CP_WAIT0()  asm volatile("cp.async.wait_group 0;" ::: "memory")

#define LDSM_X4(r0, r1, r2, r3, addr) \
    asm volatile("ldmatrix.sync.aligned.m8n8.x4.shared.b16 {%0,%1,%2,%3}, [%4];" \
                 : "=r"(r0), "=r"(r1), "=r"(r2), "=r"(r3) : "r"(addr))

#define MMA16816(d, a, b) \
    asm volatile("mma.sync.aligned.m16n8k16.row.col.f32.bf16.bf16.f32 " \
                 "{%0,%1,%2,%3}, {%4,%5,%6,%7}, {%8,%9}, {%0,%1,%2,%3};" \
                 : "+f"((d)[0]), "+f"((d)[1]), "+f"((d)[2]), "+f"((d)[3]) \
                 : "r"((a)[0]), "r"((a)[1]), "r"((a)[2]), "r"((a)[3]), \
                   "r"((b)[0]), "r"((b)[1]))

// ---------------- small helpers --------------------------------------------
__global__ void zero_norm_kernel() {
    int i = blockIdx.x * blockDim.x + threadIdx.x;
    if (i < Bq * Sq) g_norm[i] = 0.0f;
}

__global__ void sincos_kernel(const float* __restrict__ phases) {
    int i = blockIdx.x * blockDim.x + threadIdx.x;
    if (i < Sq * Hq) {
        float s, c;
        sincosf(phases[i], &s, &c);
        g_cphi[i] = c;
        g_sphi[i] = s;
    }
}

// fp32 -> bf16 hi/lo split, 4 elements per thread
__global__ __launch_bounds__(256) void split_kernel(
    const float* __restrict__ src, __nv_bfloat16* __restrict__ hi,
    __nv_bfloat16* __restrict__ lo, int n4)
{
    int i = blockIdx.x * blockDim.x + threadIdx.x;
    if (i >= n4) return;
    float4 v = ((const float4*)src)[i];
    __nv_bfloat16 h0 = __float2bfloat16(v.x);
    __nv_bfloat16 h1 = __float2bfloat16(v.y);
    __nv_bfloat16 h2 = __float2bfloat16(v.z);
    __nv_bfloat16 h3 = __float2bfloat16(v.w);
    __nv_bfloat162 hh0 = {h0, h1}, hh1 = {h2, h3};
    ((__nv_bfloat162*)hi)[i * 2 + 0] = hh0;
    ((__nv_bfloat162*)hi)[i * 2 + 1] = hh1;
    __nv_bfloat162 ll0 = {__float2bfloat16(v.x - __bfloat162float(h0)),
                          __float2bfloat16(v.y - __bfloat162float(h1))};
    __nv_bfloat162 ll1 = {__float2bfloat16(v.z - __bfloat162float(h2)),
                          __float2bfloat16(v.w - __bfloat162float(h3))};
    ((__nv_bfloat162*)lo)[i * 2 + 0] = ll0;
    ((__nv_bfloat162*)lo)[i * 2 + 1] = ll1;
}

// ---------------- unified warp-mma GEMM (bf16 hi/lo x3) ---------------------
// CTA tile 128x128, 256 threads (8 warps, 2x4), warp tile 64x32.
// K-step 32, cp.async double buffer. EPI: 0=gemm1, 1=gate, 2=clf.
#define CTILE 8192   // bytes per smem component (128 rows * 64 B)

__device__ __forceinline__ void prefetch_tiles(
    uint32_t smb, const __nv_bfloat16* __restrict__ Ahi,
    const __nv_bfloat16* __restrict__ Alo,
    const __nv_bfloat16* __restrict__ Bhi,
    const __nv_bfloat16* __restrict__ Blo,
    int mBase, int nBase, int kk, int KT, int Nr, int tid)
{
#pragma unroll
    for (int l = 0; l < 2; ++l) {
        int idx = tid + l * 256;
        int r = idx >> 2, c = idx & 3;
        uint32_t dst = smb + r * 64 + (((c + (r >> 1)) & 3) << 4);
        size_t ka = (size_t)(mBase + r) * KT + kk + c * 8;
        size_t kb = (size_t)(nBase + r) * KT + kk + c * 8;
        int bsz = ((nBase + r) < Nr) ? 16 : 0;
        CP16(dst,              Ahi + ka, 16);
        CP16(dst + CTILE,      Alo + ka, 16);
        CP16(dst + 2 * CTILE,  Bhi + kb, bsz);
        CP16(dst + 3 * CTILE,  Blo + kb, bsz);
    }
}

template <int KT, int EPI>
__global__ __launch_bounds__(256, 2) void mma_gemm_kernel(
    const __nv_bfloat16* __restrict__ Ahi, const __nv_bfloat16* __restrict__ Alo,
    const __nv_bfloat16* __restrict__ Bhi, const __nv_bfloat16* __restrict__ Blo,
    const float* __restrict__ biasv, float* __restrict__ outp, int Nr)
{
    extern __shared__ __align__(16) char dynsm[];
    uint32_t smbase = smem_u32(dynsm);

    int tid = threadIdx.x;
    int lane = tid & 31, wid = tid >> 5;
    int wr = wid >> 2, wc = wid & 3;   // warp row (0-1), warp col (0-3)
    int mBase = blockIdx.x * 128;
    int nBase = blockIdx.y * 128;

    float acc[4][4][4];
#pragma unroll
    for (int a = 0; a < 4; a++)
#pragma unroll
        for (int b = 0; b < 4; b++)
#pragma unroll
            for (int c = 0; c < 4; c++) acc[a][b][c] = 0.0f;

    const int KSTEPS = KT / 32;
    prefetch_tiles(smbase, Ahi, Alo, Bhi, Blo, mBase, nBase, 0, KT, Nr, tid);
    CP_COMMIT();

    int buf = 0;
    for (int s = 0; s < KSTEPS; ++s) {
        if (s + 1 < KSTEPS) {
            prefetch_tiles(smbase + (buf ^ 1) * 4 * CTILE, Ahi, Alo, Bhi, Blo,
                           mBase, nBase, (s + 1) * 32, KT, Nr, tid);
            CP_COMMIT();
            CP_WAIT1();
        } else {
            CP_WAIT0();
        }
        __syncthreads();

        uint32_t smA = smbase + buf * 4 * CTILE;
        uint32_t smB = smA + 2 * CTILE;
#pragma unroll
        for (int ks = 0; ks < 2; ++ks) {
            // B fragments: two x4 per component cover 4 n8 tiles
            uint32_t bh[4][2], bl[4][2];
#pragma unroll
            for (int p = 0; p < 2; ++p) {
                int rn = wc * 32 + p * 16 + ((lane >> 4) & 1) * 8 + (lane & 7);
                int cl = ks * 2 + ((lane >> 3) & 1);
                uint32_t off = rn * 64 + (((cl + (rn >> 1)) & 3) << 4);
                LDSM_X4(bh[2 * p][0], bh[2 * p][1], bh[2 * p + 1][0], bh[2 * p + 1][1], smB + off);
                LDSM_X4(bl[2 * p][0], bl[2 * p][1], bl[2 * p + 1][0], bl[2 * p + 1][1], smB + CTILE + off);
            }
#pragma unroll
            for (int mi = 0; mi < 4; ++mi) {
                int ra = wr * 64 + mi * 16 + (lane & 15);
                int cl = ks * 2 + (lane >> 4);
                uint32_t off = ra * 64 + (((cl + (ra >> 1)) & 3) << 4);
                uint32_t ah[4], al[4];
                LDSM_X4(ah[0], ah[1], ah[2], ah[3], smA + off);
                LDSM_X4(al[0], al[1], al[2], al[3], smA + CTILE + off);
#pragma unroll
                for (int ni = 0; ni < 4; ++ni) {
                    MMA16816(acc[mi][ni], ah, bh[ni]);
                    MMA16816(acc[mi][ni], ah, bl[ni]);
                    MMA16816(acc[mi][ni], al, bh[ni]);
                }
            }
        }
        __syncthreads();
        buf ^= 1;
    }

    // ---------------- epilogue ----------------
    int rbase = mBase + wr * 64 + (lane >> 2);
    int cbase = nBase + wc * 32 + (lane & 3) * 2;

    if (EPI == 0) {
        int sIdx = nBase >> 12;
#pragma unroll
        for (int mi = 0; mi < 4; ++mi) {
#pragma unroll
            for (int h = 0; h < 2; ++h) {
                int row = rbase + mi * 16 + h * 8;
                float rs = 0.0f;
#pragma unroll
                for (int ni = 0; ni < 4; ++ni) {
                    int n = cbase + ni * 8;
                    float2 bz = *(const float2*)&biasv[n];
                    float v0 = acc[mi][ni][2 * h] + bz.x;
                    float v1 = acc[mi][ni][2 * h + 1] + bz.y;
                    float g0 = expf(-v0 * v0);
                    float g1 = expf(-v1 * v1);
                    *(float2*)&g_act[(size_t)row * N1 + n] = make_float2(g0, g1);
                    rs += g0 * g0 + g1 * g1;
                }
                rs += __shfl_xor_sync(0xffffffffu, rs, 1);
                rs += __shfl_xor_sync(0xffffffffu, rs, 2);
                if ((lane & 3) == 0) atomicAdd(&g_norm[row * Sq + sIdx], rs);
            }
        }
    } else if (EPI == 1) {
#pragma unroll
        for (int mi = 0; mi < 4; ++mi) {
#pragma unroll
            for (int h = 0; h < 2; ++h) {
                int row = rbase + mi * 16 + h * 8;
#pragma unroll
                for (int ni = 0; ni < 4; ++ni) {
                    int n = cbase + ni * 8;
                    float2 bz = *(const float2*)&biasv[n];
                    float v0 = acc[mi][ni][2 * h] + bz.x;
                    float v1 = acc[mi][ni][2 * h + 1] + bz.y;
                    float g0 = 1.0f / (1.0f + expf(-v0));
                    float g1 = 1.0f / (1.0f + expf(-v1));
                    size_t idx = (size_t)row * Hq + n;
                    float2 sr = *(float2*)&g_supr[idx];
                    float2 si = *(float2*)&g_supi[idx];
                    sr.x *= g0; sr.y *= g1; si.x *= g0; si.y *= g1;
                    *(float2*)&g_supr[idx] = sr;
                    *(float2*)&g_supi[idx] = si;
                }
            }
        }
    } else {
#pragma unroll
        for (int mi = 0; mi < 4; ++mi) {
#pragma unroll
            for (int h = 0; h < 2; ++h) {
                int row = rbase + mi * 16 + h * 8;
#pragma unroll
                for (int ni = 0; ni < 4; ++ni) {
                    int n = cbase + ni * 8;
                    if (n < Nr) {
                        float2 bz = *(const float2*)&biasv[n];
                        float v0 = acc[mi][ni][2 * h] + bz.x;
                        float v1 = acc[mi][ni][2 * h + 1] + bz.y;
                        *(float2*)&outp[(size_t)row * Cq + n] = make_float2(v0, v1);
                    }
                }
            }
        }
    }
}

// ---------------- superposition: phase mix + normalize ---------------------
__global__ __launch_bounds__(256) void sup_kernel() {
    int idx = blockIdx.x * blockDim.x + threadIdx.x;  // < B*H
    int b = idx >> 11, h = idx & (Hq - 1);
    float r = 0.0f, im = 0.0f;
#pragma unroll
    for (int s = 0; s < Sq; s++) {
        float f  = rsqrtf(g_norm[b * Sq + s] + EPSq);
        float a  = g_act[(size_t)b * N1 + s * (2 * Hq) + h];
        float be = g_act[(size_t)b * N1 + s * (2 * Hq) + Hq + h];
        float c  = g_cphi[s * Hq + h];
        float sp = g_sphi[s * Hq + h];
        r  += f * (a * c - be * sp);
        im += f * (a * sp + be * c);
    }
    g_supr[idx] = r;
    g_supi[idx] = im;
}

// mag = sqrt(r^2+i^2) -> bf16 hi/lo split (input to gate GEMM)
__global__ __launch_bounds__(256) void mag_split_kernel() {
    int idx = blockIdx.x * blockDim.x + threadIdx.x;
    float r = g_supr[idx], im = g_supi[idx];
    float m = sqrtf(r * r + im * im);
    __nv_bfloat16 h = __float2bfloat16(m);
    g_mhi[idx] = h;
    g_mlo[idx] = __float2bfloat16(m - __bfloat162float(h));
}

__global__ __launch_bounds__(256) void msq_kernel() {
    int idx = blockIdx.x * blockDim.x + threadIdx.x;
    float r = g_supr[idx], im = g_supi[idx];
    g_mag[idx] = r * r + im * im;
}

// ---------------- exact top-k (k=256 of 2048) per row, jax tie semantics ---
__global__ __launch_bounds__(256) void topk_kernel() {
    __shared__ float sv[Hq];
    __shared__ int swarp[8];
    __shared__ float fwarp[8];
    __shared__ int scnt;
    __shared__ float ssum;

    int b = blockIdx.x;
    int t = threadIdx.x;
    for (int i = t; i < Hq; i += 256) sv[i] = g_mag[(size_t)b * Hq + i];
    __syncthreads();

    unsigned thr = 0u;
    for (int bit = 30; bit >= 0; --bit) {
        unsigned cand = thr | (1u << bit);
        int c = 0;
        for (int i = t; i < Hq; i += 256)
            c += (__float_as_uint(sv[i]) >= cand) ? 1 : 0;
#pragma unroll
        for (int o = 16; o; o >>= 1) c += __shfl_down_sync(0xffffffffu, c, o);
        if ((t & 31) == 0) swarp[t >> 5] = c;
        __syncthreads();
        if (t < 32) {
            int cc = (t < 8) ? swarp[t] : 0;
#pragma unroll
            for (int o = 4; o; o >>= 1) cc += __shfl_down_sync(0xffffffffu, cc, o);
            if (t == 0) scnt = cc;
        }
        __syncthreads();
        if (scnt >= TOPKq) thr = cand;
        __syncthreads();
    }
    float T = __uint_as_float(thr);

    {
        int c = 0;
        for (int i = t; i < Hq; i += 256) c += (sv[i] > T) ? 1 : 0;
#pragma unroll
        for (int o = 16; o; o >>= 1) c += __shfl_down_sync(0xffffffffu, c, o);
        if ((t & 31) == 0) swarp[t >> 5] = c;
        __syncthreads();
        if (t < 32) {
            int cc = (t < 8) ? swarp[t] : 0;
#pragma unroll
            for (int o = 4; o; o >>= 1) cc += __shfl_down_sync(0xffffffffu, cc, o);
            if (t == 0) scnt = cc;
        }
        __syncthreads();
    }
    int need_eq = TOPKq - scnt;
    __syncthreads();

    float vals[8];
    bool keep[8];
    float mysum = 0.0f;
#pragma unroll
    for (int l = 0; l < 8; l++) {
        int i = t + l * 256;
        float v = sv[i];
        bool k;
        if (v > T) k = true;
        else if (v == T) {
            int r = 0;
            for (int j = 0; j < i; j++) r += (sv[j] == T) ? 1 : 0;
            k = (r < need_eq);
        } else k = false;
        vals[l] = v;
        keep[l] = k;
        if (k) mysum += v;
    }
#pragma unroll
    for (int o = 16; o; o >>= 1) mysum += __shfl_down_sync(0xffffffffu, mysum, o);
    if ((t & 31) == 0) fwarp[t >> 5] = mysum;
    __syncthreads();
    if (t < 32) {
        float ss = (t < 8) ? fwarp[t] : 0.0f;
#pragma unroll
        for (int o = 4; o; o >>= 1) ss += __shfl_down_sync(0xffffffffu, ss, o);
        if (t == 0) ssum = ss;
    }
    __syncthreads();
    float denom = ssum + EPSq;
#pragma unroll
    for (int l = 0; l < 8; l++) {
        int i = t + l * 256;
        float p = keep[l] ? vals[l] / denom : 0.0f;
        __nv_bfloat16 h = __float2bfloat16(p);
        g_pbhi[(size_t)b * Hq + i] = h;
        g_pblo[(size_t)b * Hq + i] = __float2bfloat16(p - __bfloat162float(h));
    }
}

// ---------------- launch ----------------------------------------------------
#define GEMM_SMEM (2 * 4 * CTILE)   // 64 KB

extern "C" void kernel_launch(void* const* d_in, const int* in_sizes, int n_in,
                              void* d_out, int out_size)
{
    const float* x      = (const float*)d_in[0];
    const float* W      = (const float*)d_in[1];
    const float* bias   = (const float*)d_in[2];
    const float* phases = (const float*)d_in[3];
    const float* gate_W = (const float*)d_in[4];
    const float* gate_b = (const float*)d_in[5];
    const float* clf_W  = (const float*)d_in[6];
    const float* clf_b  = (const float*)d_in[7];
    float* out = (float*)d_out;

    cudaFuncSetAttribute(mma_gemm_kernel<Iq, 0>,
                         cudaFuncAttributeMaxDynamicSharedMemorySize, GEMM_SMEM);
    cudaFuncSetAttribute(mma_gemm_kernel<Hq, 1>,
                         cudaFuncAttributeMaxDynamicSharedMemorySize, GEMM_SMEM);
    cudaFuncSetAttribute(mma_gemm_kernel<Hq, 2>,
                         cudaFuncAttributeMaxDynamicSharedMemorySize, GEMM_SMEM);

    __nv_bfloat16 *xhi, *xlo, *whi, *wlo, *gwhi, *gwlo, *cwhi, *cwlo;
    __nv_bfloat16 *mhi, *mlo, *pbhi, *pblo;
    cudaGetSymbolAddress((void**)&xhi, g_xhi);
    cudaGetSymbolAddress((void**)&xlo, g_xlo);
    cudaGetSymbolAddress((void**)&whi, g_whi);
    cudaGetSymbolAddress((void**)&wlo, g_wlo);
    cudaGetSymbolAddress((void**)&gwhi, g_gwhi);
    cudaGetSymbolAddress((void**)&gwlo, g_gwlo);
    cudaGetSymbolAddress((void**)&cwhi, g_cwhi);
    cudaGetSymbolAddress((void**)&cwlo, g_cwlo);
    cudaGetSymbolAddress((void**)&mhi, g_mhi);
    cudaGetSymbolAddress((void**)&mlo, g_mlo);
    cudaGetSymbolAddress((void**)&pbhi, g_pbhi);
    cudaGetSymbolAddress((void**)&pblo, g_pblo);

    zero_norm_kernel<<<(Bq * Sq + 255) / 256, 256>>>();
    sincos_kernel<<<(Sq * Hq + 255) / 256, 256>>>(phases);

    split_kernel<<<((Bq * Iq / 4) + 255) / 256, 256>>>(x, xhi, xlo, Bq * Iq / 4);
    split_kernel<<<(((size_t)N1 * Iq / 4) + 255) / 256, 256>>>(W, whi, wlo, N1 * Iq / 4);
    split_kernel<<<((Hq * Hq / 4) + 255) / 256, 256>>>(gate_W, gwhi, gwlo, Hq * Hq / 4);
    split_kernel<<<((Cq * Hq / 4) + 255) / 256, 256>>>(clf_W, cwhi, cwlo, Cq * Hq / 4);

    // GEMM1: act = exp(-(x @ W^T + b)^2) fused
    mma_gemm_kernel<Iq, 0><<<dim3(Bq / 128, N1 / 128), 256, GEMM_SMEM>>>(
        xhi, xlo, whi, wlo, bias, nullptr, N1);

    sup_kernel<<<(Bq * Hq) / 256, 256>>>();

    for (int step = 0; step < 2; step++) {
        mag_split_kernel<<<(Bq * Hq) / 256, 256>>>();
        mma_gemm_kernel<Hq, 1><<<dim3(Bq / 128, Hq / 128), 256, GEMM_SMEM>>>(
            mhi, mlo, gwhi, gwlo, gate_b, nullptr, Hq);
    }

    msq_kernel<<<(Bq * Hq) / 256, 256>>>();
    topk_kernel<<<Bq, 256>>>();

    mma_gemm_kernel<Hq, 2><<<dim3(Bq / 128, (Cq + 127) / 128), 256, GEMM_SMEM>>>(
        pbhi, pblo, cwhi, cwlo, clf_b, out, Cq);
}

// round 6
// speedup vs baseline: 2.7947x; 1.0178x over previous
#include <cuda_runtime.h>
#include <cuda_bf16.h>
#include <math.h>
#include <stdint.h>

// Problem constants
#define Bq 2048
#define Iq 1024
#define Hq 2048
#define Cq 1000
#define Sq 8
#define N1 (Sq * 2 * Hq)   // 32768
#define TOPKq 256
#define EPSq 1e-8f

// ---------------- scratch (device globals; no allocation allowed) ----------
__device__ float g_act[(size_t)Bq * N1];
__device__ float g_norm[Bq * Sq];
__device__ float g_cphi[Sq * Hq];
__device__ float g_sphi[Sq * Hq];
__device__ float g_supr[Bq * Hq];
__device__ float g_supi[Bq * Hq];

// bf16 hi/lo splits for tensor-core fp32 emulation
__device__ __align__(16) __nv_bfloat16 g_xhi[(size_t)Bq * Iq];
__device__ __align__(16) __nv_bfloat16 g_xlo[(size_t)Bq * Iq];
__device__ __align__(16) __nv_bfloat16 g_whi[(size_t)N1 * Iq];
__device__ __align__(16) __nv_bfloat16 g_wlo[(size_t)N1 * Iq];
__device__ __align__(16) __nv_bfloat16 g_gwhi[(size_t)Hq * Hq];
__device__ __align__(16) __nv_bfloat16 g_gwlo[(size_t)Hq * Hq];
__device__ __align__(16) __nv_bfloat16 g_cwhi[(size_t)Cq * Hq];
__device__ __align__(16) __nv_bfloat16 g_cwlo[(size_t)Cq * Hq];
__device__ __align__(16) __nv_bfloat16 g_mhi[(size_t)Bq * Hq];
__device__ __align__(16) __nv_bfloat16 g_mlo[(size_t)Bq * Hq];
__device__ __align__(16) __nv_bfloat16 g_pbhi[(size_t)Bq * Hq];
__device__ __align__(16) __nv_bfloat16 g_pblo[(size_t)Bq * Hq];

// ---------------- PTX helpers ----------------------------------------------
__device__ __forceinline__ uint32_t smem_u32(const void* p) {
    uint32_t a;
    asm("{ .reg .u64 t; cvta.to.shared.u64 t, %1; cvt.u32.u64 %0, t; }" : "=r"(a) : "l"(p));
    return a;
}

#define CP16(dst, src, szr) \
    asm volatile("cp.async.cg.shared.global [%0], [%1], 16, %2;" \
                 :: "r"(dst), "l"(src), "r"(szr) : "memory")
#define CP_COMMIT() asm volatile("cp.async.commit_group;" ::: "memory")
#define CP_WAIT1()  asm volatile("cp.async.wait_group 1;" ::: "memory")

#define LDSM_X4(r0, r1, r2, r3, addr) \
    asm volatile("ldmatrix.sync.aligned.m8n8.x4.shared.b16 {%0,%1,%2,%3}, [%4];" \
                 : "=r"(r0), "=r"(r1), "=r"(r2), "=r"(r3) : "r"(addr))

#define MMA16816(d, a, b) \
    asm volatile("mma.sync.aligned.m16n8k16.row.col.f32.bf16.bf16.f32 " \
                 "{%0,%1,%2,%3}, {%4,%5,%6,%7}, {%8,%9}, {%0,%1,%2,%3};" \
                 : "+f"((d)[0]), "+f"((d)[1]), "+f"((d)[2]), "+f"((d)[3]) \
                 : "r"((a)[0]), "r"((a)[1]), "r"((a)[2]), "r"((a)[3]), \
                   "r"((b)[0]), "r"((b)[1]))

// ---------------- small helpers --------------------------------------------
__global__ void zero_norm_kernel() {
    int i = blockIdx.x * blockDim.x + threadIdx.x;
    if (i < Bq * Sq) g_norm[i] = 0.0f;
}

__global__ void sincos_kernel(const float* __restrict__ phases) {
    int i = blockIdx.x * blockDim.x + threadIdx.x;
    if (i < Sq * Hq) {
        float s, c;
        sincosf(phases[i], &s, &c);
        g_cphi[i] = c;
        g_sphi[i] = s;
    }
}

// fp32 -> bf16 hi/lo split, 4 elements per thread
__global__ __launch_bounds__(256) void split_kernel(
    const float* __restrict__ src, __nv_bfloat16* __restrict__ hi,
    __nv_bfloat16* __restrict__ lo, int n4)
{
    int i = blockIdx.x * blockDim.x + threadIdx.x;
    if (i >= n4) return;
    float4 v = ((const float4*)src)[i];
    __nv_bfloat16 h0 = __float2bfloat16(v.x);
    __nv_bfloat16 h1 = __float2bfloat16(v.y);
    __nv_bfloat16 h2 = __float2bfloat16(v.z);
    __nv_bfloat16 h3 = __float2bfloat16(v.w);
    __nv_bfloat162 hh0 = {h0, h1}, hh1 = {h2, h3};
    ((__nv_bfloat162*)hi)[i * 2 + 0] = hh0;
    ((__nv_bfloat162*)hi)[i * 2 + 1] = hh1;
    __nv_bfloat162 ll0 = {__float2bfloat16(v.x - __bfloat162float(h0)),
                          __float2bfloat16(v.y - __bfloat162float(h1))};
    __nv_bfloat162 ll1 = {__float2bfloat16(v.z - __bfloat162float(h2)),
                          __float2bfloat16(v.w - __bfloat162float(h3))};
    ((__nv_bfloat162*)lo)[i * 2 + 0] = ll0;
    ((__nv_bfloat162*)lo)[i * 2 + 1] = ll1;
}

// ---------------- unified warp-mma GEMM ------------------------------------
// CTA tile 128x128, 256 threads (8 warps, 2x4), warp tile 64x32.
// K-step 32, cp.async 3-stage pipeline. EPI: 0=gemm1, 1=gate, 2=clf.
#define CTILE 8192   // bytes per smem component (128 rows * 64 B)

__device__ __forceinline__ void prefetch_tiles(
    uint32_t smb, const __nv_bfloat16* __restrict__ Ahi,
    const __nv_bfloat16* __restrict__ Alo,
    const __nv_bfloat16* __restrict__ Bhi,
    const __nv_bfloat16* __restrict__ Blo,
    int mBase, int nBase, int kk, int KT, int Nr, int tid)
{
#pragma unroll
    for (int l = 0; l < 2; ++l) {
        int idx = tid + l * 256;
        int r = idx >> 2, c = idx & 3;
        uint32_t dst = smb + r * 64 + (((c + (r >> 1)) & 3) << 4);
        size_t ka = (size_t)(mBase + r) * KT + kk + c * 8;
        size_t kb = (size_t)(nBase + r) * KT + kk + c * 8;
        int bsz = ((nBase + r) < Nr) ? 16 : 0;
        CP16(dst,              Ahi + ka, 16);
        CP16(dst + CTILE,      Alo + ka, 16);
        CP16(dst + 2 * CTILE,  Bhi + kb, bsz);
        CP16(dst + 3 * CTILE,  Blo + kb, bsz);
    }
}

template <int KT, int EPI>
__global__ __launch_bounds__(256, 2) void mma_gemm_kernel(
    const __nv_bfloat16* __restrict__ Ahi, const __nv_bfloat16* __restrict__ Alo,
    const __nv_bfloat16* __restrict__ Bhi, const __nv_bfloat16* __restrict__ Blo,
    const float* __restrict__ biasv, float* __restrict__ outp, int Nr)
{
    extern __shared__ __align__(16) char dynsm[];
    uint32_t smbase = smem_u32(dynsm);
    const int STAGE = 4 * CTILE;

    int tid = threadIdx.x;
    int lane = tid & 31, wid = tid >> 5;
    int wr = wid >> 2, wc = wid & 3;
    int mBase = blockIdx.x * 128;
    int nBase = blockIdx.y * 128;

    float acc[4][4][4];
#pragma unroll
    for (int a = 0; a < 4; a++)
#pragma unroll
        for (int b = 0; b < 4; b++)
#pragma unroll
            for (int c = 0; c < 4; c++) acc[a][b][c] = 0.0f;

    const int KSTEPS = KT / 32;
    prefetch_tiles(smbase, Ahi, Alo, Bhi, Blo, mBase, nBase, 0, KT, Nr, tid);
    CP_COMMIT();
    prefetch_tiles(smbase + STAGE, Ahi, Alo, Bhi, Blo, mBase, nBase, 32, KT, Nr, tid);
    CP_COMMIT();

    for (int s = 0; s < KSTEPS; ++s) {
        CP_WAIT1();
        __syncthreads();

        if (s + 2 < KSTEPS)
            prefetch_tiles(smbase + ((s + 2) % 3) * STAGE, Ahi, Alo, Bhi, Blo,
                           mBase, nBase, (s + 2) * 32, KT, Nr, tid);
        CP_COMMIT();

        uint32_t smA = smbase + (s % 3) * STAGE;
        uint32_t smB = smA + 2 * CTILE;
#pragma unroll
        for (int ks = 0; ks < 2; ++ks) {
            uint32_t bh[4][2], bl[4][2];
#pragma unroll
            for (int p = 0; p < 2; ++p) {
                int rn = wc * 32 + p * 16 + ((lane >> 4) & 1) * 8 + (lane & 7);
                int cl = ks * 2 + ((lane >> 3) & 1);
                uint32_t off = rn * 64 + (((cl + (rn >> 1)) & 3) << 4);
                LDSM_X4(bh[2 * p][0], bh[2 * p][1], bh[2 * p + 1][0], bh[2 * p + 1][1], smB + off);
                LDSM_X4(bl[2 * p][0], bl[2 * p][1], bl[2 * p + 1][0], bl[2 * p + 1][1],
                        smB + CTILE + off);
            }
#pragma unroll
            for (int mi = 0; mi < 4; ++mi) {
                int ra = wr * 64 + mi * 16 + (lane & 15);
                int cl = ks * 2 + (lane >> 4);
                uint32_t off = ra * 64 + (((cl + (ra >> 1)) & 3) << 4);
                uint32_t ah[4], al[4];
                LDSM_X4(ah[0], ah[1], ah[2], ah[3], smA + off);
                LDSM_X4(al[0], al[1], al[2], al[3], smA + CTILE + off);
#pragma unroll
                for (int ni = 0; ni < 4; ++ni) {
                    MMA16816(acc[mi][ni], ah, bh[ni]);
                    MMA16816(acc[mi][ni], ah, bl[ni]);
                    MMA16816(acc[mi][ni], al, bh[ni]);
                }
            }
        }
    }

    // ---------------- epilogue ----------------
    int rbase = mBase + wr * 64 + (lane >> 2);
    int cbase = nBase + wc * 32 + (lane & 3) * 2;

    if (EPI == 0) {
        int sIdx = nBase >> 12;
#pragma unroll
        for (int mi = 0; mi < 4; ++mi) {
#pragma unroll
            for (int h = 0; h < 2; ++h) {
                int row = rbase + mi * 16 + h * 8;
                float rs = 0.0f;
#pragma unroll
                for (int ni = 0; ni < 4; ++ni) {
                    int n = cbase + ni * 8;
                    float2 bz = *(const float2*)&biasv[n];
                    float v0 = acc[mi][ni][2 * h] + bz.x;
                    float v1 = acc[mi][ni][2 * h + 1] + bz.y;
                    float g0 = expf(-v0 * v0);
                    float g1 = expf(-v1 * v1);
                    *(float2*)&g_act[(size_t)row * N1 + n] = make_float2(g0, g1);
                    rs += g0 * g0 + g1 * g1;
                }
                rs += __shfl_xor_sync(0xffffffffu, rs, 1);
                rs += __shfl_xor_sync(0xffffffffu, rs, 2);
                if ((lane & 3) == 0) atomicAdd(&g_norm[row * Sq + sIdx], rs);
            }
        }
    } else if (EPI == 1) {
        // gate: update supr/supi in place (no other global writes -> no race)
#pragma unroll
        for (int mi = 0; mi < 4; ++mi) {
#pragma unroll
            for (int h = 0; h < 2; ++h) {
                int row = rbase + mi * 16 + h * 8;
#pragma unroll
                for (int ni = 0; ni < 4; ++ni) {
                    int n = cbase + ni * 8;
                    float2 bz = *(const float2*)&biasv[n];
                    float v0 = acc[mi][ni][2 * h] + bz.x;
                    float v1 = acc[mi][ni][2 * h + 1] + bz.y;
                    float g0 = 1.0f / (1.0f + expf(-v0));
                    float g1 = 1.0f / (1.0f + expf(-v1));
                    size_t idx = (size_t)row * Hq + n;
                    float2 sr = *(float2*)&g_supr[idx];
                    float2 si = *(float2*)&g_supi[idx];
                    sr.x *= g0; sr.y *= g1; si.x *= g0; si.y *= g1;
                    *(float2*)&g_supr[idx] = sr;
                    *(float2*)&g_supi[idx] = si;
                }
            }
        }
    } else {
#pragma unroll
        for (int mi = 0; mi < 4; ++mi) {
#pragma unroll
            for (int h = 0; h < 2; ++h) {
                int row = rbase + mi * 16 + h * 8;
#pragma unroll
                for (int ni = 0; ni < 4; ++ni) {
                    int n = cbase + ni * 8;
                    if (n < Nr) {
                        float2 bz = *(const float2*)&biasv[n];
                        float v0 = acc[mi][ni][2 * h] + bz.x;
                        float v1 = acc[mi][ni][2 * h + 1] + bz.y;
                        *(float2*)&outp[(size_t)row * Cq + n] = make_float2(v0, v1);
                    }
                }
            }
        }
    }
}

// ---------------- superposition: phase mix + normalize ---------------------
// also emits mag hi/lo for the FIRST gate step (kernel boundary = sync, no race)
__global__ __launch_bounds__(256) void sup_kernel() {
    int idx = blockIdx.x * blockDim.x + threadIdx.x;
    int b = idx >> 11, h = idx & (Hq - 1);
    float r = 0.0f, im = 0.0f;
#pragma unroll
    for (int s = 0; s < Sq; s++) {
        float f  = rsqrtf(g_norm[b * Sq + s] + EPSq);
        float a  = g_act[(size_t)b * N1 + s * (2 * Hq) + h];
        float be = g_act[(size_t)b * N1 + s * (2 * Hq) + Hq + h];
        float c  = g_cphi[s * Hq + h];
        float sp = g_sphi[s * Hq + h];
        r  += f * (a * c - be * sp);
        im += f * (a * sp + be * c);
    }
    g_supr[idx] = r;
    g_supi[idx] = im;
    float m = sqrtf(r * r + im * im);
    __nv_bfloat16 mh = __float2bfloat16(m);
    g_mhi[idx] = mh;
    g_mlo[idx] = __float2bfloat16(m - __bfloat162float(mh));
}

// mag hi/lo regeneration between gate steps (separate kernel -> no race)
__global__ __launch_bounds__(256) void mag_split_kernel() {
    int idx = blockIdx.x * blockDim.x + threadIdx.x;
    float r = g_supr[idx], im = g_supi[idx];
    float m = sqrtf(r * r + im * im);
    __nv_bfloat16 mh = __float2bfloat16(m);
    g_mhi[idx] = mh;
    g_mlo[idx] = __float2bfloat16(m - __bfloat162float(mh));
}

// ---------------- exact top-k (k=256 of 2048), msq fused --------------------
__global__ __launch_bounds__(256) void topk_kernel() {
    __shared__ float sv[Hq];
    __shared__ int swarp[8];
    __shared__ float fwarp[8];
    __shared__ int scnt;
    __shared__ float ssum;

    int b = blockIdx.x;
    int t = threadIdx.x;
    for (int i = t; i < Hq; i += 256) {
        float r = g_supr[(size_t)b * Hq + i];
        float im = g_supi[(size_t)b * Hq + i];
        sv[i] = r * r + im * im;
    }
    __syncthreads();

    unsigned thr = 0u;
    for (int bit = 30; bit >= 0; --bit) {
        unsigned cand = thr | (1u << bit);
        int c = 0;
        for (int i = t; i < Hq; i += 256)
            c += (__float_as_uint(sv[i]) >= cand) ? 1 : 0;
#pragma unroll
        for (int o = 16; o; o >>= 1) c += __shfl_down_sync(0xffffffffu, c, o);
        if ((t & 31) == 0) swarp[t >> 5] = c;
        __syncthreads();
        if (t < 32) {
            int cc = (t < 8) ? swarp[t] : 0;
#pragma unroll
            for (int o = 4; o; o >>= 1) cc += __shfl_down_sync(0xffffffffu, cc, o);
            if (t == 0) scnt = cc;
        }
        __syncthreads();
        if (scnt >= TOPKq) thr = cand;
        __syncthreads();
    }
    float T = __uint_as_float(thr);

    {
        int c = 0;
        for (int i = t; i < Hq; i += 256) c += (sv[i] > T) ? 1 : 0;
#pragma unroll
        for (int o = 16; o; o >>= 1) c += __shfl_down_sync(0xffffffffu, c, o);
        if ((t & 31) == 0) swarp[t >> 5] = c;
        __syncthreads();
        if (t < 32) {
            int cc = (t < 8) ? swarp[t] : 0;
#pragma unroll
            for (int o = 4; o; o >>= 1) cc += __shfl_down_sync(0xffffffffu, cc, o);
            if (t == 0) scnt = cc;
        }
        __syncthreads();
    }
    int need_eq = TOPKq - scnt;
    __syncthreads();

    float vals[8];
    bool keep[8];
    float mysum = 0.0f;
#pragma unroll
    for (int l = 0; l < 8; l++) {
        int i = t + l * 256;
        float v = sv[i];
        bool k;
        if (v > T) k = true;
        else if (v == T) {
            int r = 0;
            for (int j = 0; j < i; j++) r += (sv[j] == T) ? 1 : 0;
            k = (r < need_eq);
        } else k = false;
        vals[l] = v;
        keep[l] = k;
        if (k) mysum += v;
    }
#pragma unroll
    for (int o = 16; o; o >>= 1) mysum += __shfl_down_sync(0xffffffffu, mysum, o);
    if ((t & 31) == 0) fwarp[t >> 5] = mysum;
    __syncthreads();
    if (t < 32) {
        float ss = (t < 8) ? fwarp[t] : 0.0f;
#pragma unroll
        for (int o = 4; o; o >>= 1) ss += __shfl_down_sync(0xffffffffu, ss, o);
        if (t == 0) ssum = ss;
    }
    __syncthreads();
    float denom = ssum + EPSq;
#pragma unroll
    for (int l = 0; l < 8; l++) {
        int i = t + l * 256;
        float p = keep[l] ? vals[l] / denom : 0.0f;
        __nv_bfloat16 h = __float2bfloat16(p);
        g_pbhi[(size_t)b * Hq + i] = h;
        g_pblo[(size_t)b * Hq + i] = __float2bfloat16(p - __bfloat162float(h));
    }
}

// ---------------- launch ----------------------------------------------------
#define GEMM_SMEM (3 * 4 * CTILE)   // 96 KB

extern "C" void kernel_launch(void* const* d_in, const int* in_sizes, int n_in,
                              void* d_out, int out_size)
{
    const float* x      = (const float*)d_in[0];
    const float* W      = (const float*)d_in[1];
    const float* bias   = (const float*)d_in[2];
    const float* phases = (const float*)d_in[3];
    const float* gate_W = (const float*)d_in[4];
    const float* gate_b = (const float*)d_in[5];
    const float* clf_W  = (const float*)d_in[6];
    const float* clf_b  = (const float*)d_in[7];
    float* out = (float*)d_out;

    cudaFuncSetAttribute(mma_gemm_kernel<Iq, 0>,
                         cudaFuncAttributeMaxDynamicSharedMemorySize, GEMM_SMEM);
    cudaFuncSetAttribute(mma_gemm_kernel<Hq, 1>,
                         cudaFuncAttributeMaxDynamicSharedMemorySize, GEMM_SMEM);
    cudaFuncSetAttribute(mma_gemm_kernel<Hq, 2>,
                         cudaFuncAttributeMaxDynamicSharedMemorySize, GEMM_SMEM);

    __nv_bfloat16 *xhi, *xlo, *whi, *wlo, *gwhi, *gwlo, *cwhi, *cwlo;
    __nv_bfloat16 *mhi, *mlo, *pbhi, *pblo;
    cudaGetSymbolAddress((void**)&xhi, g_xhi);
    cudaGetSymbolAddress((void**)&xlo, g_xlo);
    cudaGetSymbolAddress((void**)&whi, g_whi);
    cudaGetSymbolAddress((void**)&wlo, g_wlo);
    cudaGetSymbolAddress((void**)&gwhi, g_gwhi);
    cudaGetSymbolAddress((void**)&gwlo, g_gwlo);
    cudaGetSymbolAddress((void**)&cwhi, g_cwhi);
    cudaGetSymbolAddress((void**)&cwlo, g_cwlo);
    cudaGetSymbolAddress((void**)&mhi, g_mhi);
    cudaGetSymbolAddress((void**)&mlo, g_mlo);
    cudaGetSymbolAddress((void**)&pbhi, g_pbhi);
    cudaGetSymbolAddress((void**)&pblo, g_pblo);

    zero_norm_kernel<<<(Bq * Sq + 255) / 256, 256>>>();
    sincos_kernel<<<(Sq * Hq + 255) / 256, 256>>>(phases);

    split_kernel<<<((Bq * Iq / 4) + 255) / 256, 256>>>(x, xhi, xlo, Bq * Iq / 4);
    split_kernel<<<(((size_t)N1 * Iq / 4) + 255) / 256, 256>>>(W, whi, wlo, N1 * Iq / 4);
    split_kernel<<<((Hq * Hq / 4) + 255) / 256, 256>>>(gate_W, gwhi, gwlo, Hq * Hq / 4);
    split_kernel<<<((Cq * Hq / 4) + 255) / 256, 256>>>(clf_W, cwhi, cwlo, Cq * Hq / 4);

    // GEMM1: act = exp(-(x @ W^T + b)^2), 3-term fp32 emulation
    mma_gemm_kernel<Iq, 0><<<dim3(Bq / 128, N1 / 128), 256, GEMM_SMEM>>>(
        xhi, xlo, whi, wlo, bias, nullptr, N1);

    // sup + first mag split fused (safe: kernel boundary before gate reads)
    sup_kernel<<<(Bq * Hq) / 256, 256>>>();

    // gate step 0
    mma_gemm_kernel<Hq, 1><<<dim3(Bq / 128, Hq / 128), 256, GEMM_SMEM>>>(
        mhi, mlo, gwhi, gwlo, gate_b, nullptr, Hq);
    // regenerate mag between steps (separate kernel -> no in-place race)
    mag_split_kernel<<<(Bq * Hq) / 256, 256>>>();
    // gate step 1
    mma_gemm_kernel<Hq, 1><<<dim3(Bq / 128, Hq / 128), 256, GEMM_SMEM>>>(
        mhi, mlo, gwhi, gwlo, gate_b, nullptr, Hq);

    topk_kernel<<<Bq, 256>>>();

    mma_gemm_kernel<Hq, 2><<<dim3(Bq / 128, (Cq + 127) / 128), 256, GEMM_SMEM>>>(
        pbhi, pblo, cwhi, cwlo, clf_b, out, Cq);
}